// round 8
// baseline (speedup 1.0000x reference)
#include <cuda_runtime.h>
#include <math.h>

#define WFULL 0xffffffffu
typedef unsigned long long ull;

// ---- packed fp32x2 helpers (SASS FFMA2 path, ptxas won't emit from C++) ----
__device__ __forceinline__ float2 f2fma(float2 a, float2 b, float2 c) {
    float2 d;
    asm("fma.rn.f32x2 %0, %1, %2, %3;"
        : "=l"(reinterpret_cast<ull&>(d))
        : "l"(reinterpret_cast<ull&>(a)),
          "l"(reinterpret_cast<ull&>(b)),
          "l"(reinterpret_cast<ull&>(c)));
    return d;
}
__device__ __forceinline__ float2 f2mul(float2 a, float2 b) {
    float2 d;
    asm("mul.rn.f32x2 %0, %1, %2;"
        : "=l"(reinterpret_cast<ull&>(d))
        : "l"(reinterpret_cast<ull&>(a)),
          "l"(reinterpret_cast<ull&>(b)));
    return d;
}

// Fast-Givens rotation of this lane's pair. Columns stored SCALED: true
// column = gamma * stored. da/db/dot are TRUE quantities. Rotation:
//   A' = A - (tt*gb/ga) B ;  B' = B + (tt*ga/gb) A ;  ga*=c, gb*=c
// -> 2 f2fma per k instead of 4 issues (no c-multiplies).
__device__ __forceinline__ void rotate_pair(float2 (&A)[32], float2 (&B)[32],
                                            float& da, float& db,
                                            float& ga, float& gb, bool& rot_any)
{
    float2 acc0 = {0.f,0.f}, acc1 = {0.f,0.f}, acc2 = {0.f,0.f}, acc3 = {0.f,0.f};
#pragma unroll
    for (int k = 0; k < 32; k += 4) {
        acc0 = f2fma(A[k],   B[k],   acc0);
        acc1 = f2fma(A[k+1], B[k+1], acc1);
        acc2 = f2fma(A[k+2], B[k+2], acc2);
        acc3 = f2fma(A[k+3], B[k+3], acc3);
    }
    float sdot = ((acc0.x+acc0.y)+(acc1.x+acc1.y)) + ((acc2.x+acc2.y)+(acc3.x+acc3.y));
    float dot  = ga * gb * sdot;   // true dot (scale first: no overflow)

    if (dot*dot > 1e-8f * da * db) {
        float tau = (db - da) / (2.0f * dot);
        float tt  = 1.0f / (fabsf(tau) + sqrtf(fmaf(tau, tau, 1.0f)));
        tt = copysignf(tt, tau);
        float c  = rsqrtf(fmaf(tt, tt, 1.0f));
        float fp = tt * gb * __frcp_rn(ga);
        float fq = tt * ga * __frcp_rn(gb);
        float2 nfp2 = {-fp,-fp}, fq2 = {fq,fq};
#pragma unroll
        for (int k = 0; k < 32; k++) {
            float2 a = A[k];
            A[k] = f2fma(nfp2, B[k], a);
            B[k] = f2fma(fq2,  a,    B[k]);
        }
        da = fmaf(-tt, dot, da);
        db = fmaf( tt, dot, db);
        ga *= c;  gb *= c;
        rot_any = true;
    }
}

// Fold scales into columns and compute exact true norms (sweep-start refresh).
__device__ __forceinline__ void fold_and_norms(float2 (&A)[32], float2 (&B)[32],
                                               float& da, float& db,
                                               float& ga, float& gb)
{
    float2 ga2 = {ga,ga}, gb2 = {gb,gb};
    float2 na0={0,0}, na1={0,0}, nb0={0,0}, nb1={0,0};
#pragma unroll
    for (int k = 0; k < 32; k += 2) {
        A[k]   = f2mul(ga2, A[k]);
        A[k+1] = f2mul(ga2, A[k+1]);
        B[k]   = f2mul(gb2, B[k]);
        B[k+1] = f2mul(gb2, B[k+1]);
        na0 = f2fma(A[k],   A[k],   na0);
        na1 = f2fma(A[k+1], A[k+1], na1);
        nb0 = f2fma(B[k],   B[k],   nb0);
        nb1 = f2fma(B[k+1], B[k+1], nb1);
    }
    da = (na0.x+na0.y)+(na1.x+na1.y);
    db = (nb0.x+nb0.y)+(nb1.x+nb1.y);
    ga = 1.0f;  gb = 1.0f;
}

#define SSTR 66   // smem row stride (floats); even for float2 loads

// One warp per 64x64 SPD matrix. One-sided Jacobi, recursive cross-set
// tournament (63 rounds = all 2016 pairs), fast-Givens scaled rotations.
// Column order is scrambled — harmless: logm = sum_i w_i g_i g_i^T.
__global__ __launch_bounds__(32, 12)
void logeig_jacobi(const float* __restrict__ X, float* __restrict__ Out, int nmat)
{
    const int lane = threadIdx.x & 31;
    const int mat  = blockIdx.x;

    __shared__ float sh[64 * SSTR + 64];

    if (mat >= nmat) return;

    const float* Xm = X + (size_t)mat * 4096;
    float*       Om = Out + (size_t)mat * 4096;

    float2 A[32], B[32];

    // X symmetric: column j == row j (contiguous). Lane holds cols lane, lane+32.
    {
        const float4* rT = reinterpret_cast<const float4*>(Xm + lane * 64);
        const float4* rB = reinterpret_cast<const float4*>(Xm + (lane + 32) * 64);
#pragma unroll
        for (int m = 0; m < 16; m++) {
            float4 a = rT[m];
            A[2*m]   = make_float2(a.x, a.y);
            A[2*m+1] = make_float2(a.z, a.w);
            float4 b = rB[m];
            B[2*m]   = make_float2(b.x, b.y);
            B[2*m+1] = make_float2(b.z, b.w);
        }
    }

    float da, db;
    float ga = 1.0f, gb = 1.0f;

    for (int sweep = 0; sweep < 16; sweep++) {
        fold_and_norms(A, B, da, db, ga, gb);
        bool rot_any = false;

#pragma unroll 1
        for (int G = 32; G > 1; G >>= 1) {
            const int g   = lane & (G - 1);
            const int src = (lane ^ g) | ((g + 1) & (G - 1));   // next lane in group

#pragma unroll 1
            for (int r = 0; r < G; r++) {
                if (r) {                 // cycle B within group: pure shuffles
#pragma unroll
                    for (int k = 0; k < 32; k++) {
                        float2 v = B[k];
                        v.x = __shfl_sync(WFULL, v.x, src);
                        v.y = __shfl_sync(WFULL, v.y, src);
                        B[k] = v;
                    }
                    db = __shfl_sync(WFULL, db, src);
                    gb = __shfl_sync(WFULL, gb, src);
                }
                rotate_pair(A, B, da, db, ga, gb, rot_any);
            }

            // Regroup: sub-lanes [0,G/2) collect the A-set, [G/2,G) the B-set.
            {
                const int  h  = G >> 1;
                const bool hi = (lane & h) != 0;
#pragma unroll
                for (int k = 0; k < 32; k++) {
                    float2 a = A[k], b = B[k];
                    float sx = hi ? a.x : b.x;
                    float sy = hi ? a.y : b.y;
                    sx = __shfl_xor_sync(WFULL, sx, h);
                    sy = __shfl_xor_sync(WFULL, sy, h);
                    if (hi) A[k] = make_float2(sx, sy);
                    else    B[k] = make_float2(sx, sy);
                }
                float sd = hi ? da : db;
                float sg = hi ? ga : gb;
                sd = __shfl_xor_sync(WFULL, sd, h);
                sg = __shfl_xor_sync(WFULL, sg, h);
                if (hi) { da = sd; ga = sg; }
                else    { db = sd; gb = sg; }
            }
        }
        rotate_pair(A, B, da, db, ga, gb, rot_any);   // level G==1: local pair

        if (!__any_sync(WFULL, rot_any)) break;
    }

    // ---- Reconstruction: Out = sum_i w_i g_i g_i^T,  w_i = 0.5*log(d_i)/d_i ----
    fold_and_norms(A, B, da, db, ga, gb);   // unscale + exact lambda_i^2

    float* S = sh;                           // S[k*SSTR + slot] = g_slot[k]
    float* w = sh + 64 * SSTR;
#pragma unroll
    for (int k = 0; k < 32; k++) {
        S[(2*k  )*SSTR + lane]      = A[k].x;
        S[(2*k+1)*SSTR + lane]      = A[k].y;
        S[(2*k  )*SSTR + lane + 32] = B[k].x;
        S[(2*k+1)*SSTR + lane + 32] = B[k].y;
    }
    w[lane]      = 0.5f * logf(da) / da;
    w[lane + 32] = 0.5f * logf(db) / db;
    __syncwarp();

    // Reuse A/B registers: A[k] = w.*g[row lane], B[k] = w.*g[row lane+32]
#pragma unroll
    for (int k = 0; k < 32; k++) {
        float2 wk = *reinterpret_cast<const float2*>(w + 2*k);
        float2 g0 = *reinterpret_cast<const float2*>(S + lane*SSTR + 2*k);
        float2 g1 = *reinterpret_cast<const float2*>(S + (lane+32)*SSTR + 2*k);
        A[k] = f2mul(wk, g0);
        B[k] = f2mul(wk, g1);
    }

#pragma unroll 1
    for (int c = 0; c < 64; c += 2) {
        const float2* Sc0 = reinterpret_cast<const float2*>(S + c*SSTR);       // broadcast
        const float2* Sc1 = reinterpret_cast<const float2*>(S + (c+1)*SSTR);
        float2 s0a={0,0}, s0b={0,0}, s1a={0,0}, s1b={0,0};
#pragma unroll
        for (int k = 0; k < 32; k++) {
            float2 g0 = Sc0[k], g1 = Sc1[k];
            s0a = f2fma(A[k], g0, s0a);
            s0b = f2fma(A[k], g1, s0b);
            s1a = f2fma(B[k], g0, s1a);
            s1b = f2fma(B[k], g1, s1b);
        }
        float2 o0 = make_float2(s0a.x+s0a.y, s0b.x+s0b.y);
        float2 o1 = make_float2(s1a.x+s1a.y, s1b.x+s1b.y);
        *reinterpret_cast<float2*>(Om + lane*64 + c)        = o0;   // STG.64
        *reinterpret_cast<float2*>(Om + (lane + 32)*64 + c) = o1;
    }
}

extern "C" void kernel_launch(void* const* d_in, const int* in_sizes, int n_in,
                              void* d_out, int out_size)
{
    const float* X  = (const float*)d_in[0];
    float*       Om = (float*)d_out;
    int nmat = in_sizes[0] / 4096;          // 8192 matrices of 64x64
    logeig_jacobi<<<nmat, 32>>>(X, Om, nmat);
}

// round 13
// speedup vs baseline: 1.0724x; 1.0724x over previous
#include <cuda_runtime.h>
#include <math.h>

#define WFULL 0xffffffffu
typedef unsigned long long ull;

// ---- packed fp32x2 helpers (SASS FFMA2 path, ptxas won't emit from C++) ----
__device__ __forceinline__ float2 f2fma(float2 a, float2 b, float2 c) {
    float2 d;
    asm("fma.rn.f32x2 %0, %1, %2, %3;"
        : "=l"(reinterpret_cast<ull&>(d))
        : "l"(reinterpret_cast<ull&>(a)),
          "l"(reinterpret_cast<ull&>(b)),
          "l"(reinterpret_cast<ull&>(c)));
    return d;
}
__device__ __forceinline__ float2 f2mul(float2 a, float2 b) {
    float2 d;
    asm("mul.rn.f32x2 %0, %1, %2;"
        : "=l"(reinterpret_cast<ull&>(d))
        : "l"(reinterpret_cast<ull&>(a)),
          "l"(reinterpret_cast<ull&>(b)));
    return d;
}

// Fast-Givens rotation of this lane's pair. Columns stored SCALED: true
// column = gamma * stored. da/db/dot are TRUE quantities. Rotation:
//   A' = A - (tt*gb/ga) B ;  B' = B + (tt*ga/gb) A ;  ga*=c, gb*=c
// -> 2 f2fma per element-pair instead of 4 packed issues.
__device__ __forceinline__ void rotate_pair(float2 (&A)[32], float2 (&B)[32],
                                            float& da, float& db,
                                            float& ga, float& gb, bool& rot_any)
{
    float2 acc0 = {0.f,0.f}, acc1 = {0.f,0.f}, acc2 = {0.f,0.f}, acc3 = {0.f,0.f};
#pragma unroll
    for (int k = 0; k < 32; k += 4) {
        acc0 = f2fma(A[k],   B[k],   acc0);
        acc1 = f2fma(A[k+1], B[k+1], acc1);
        acc2 = f2fma(A[k+2], B[k+2], acc2);
        acc3 = f2fma(A[k+3], B[k+3], acc3);
    }
    float sdot = ((acc0.x+acc0.y)+(acc1.x+acc1.y)) + ((acc2.x+acc2.y)+(acc3.x+acc3.y));
    float dot  = ga * gb * sdot;   // true dot (scale first: no overflow)

    if (dot*dot > 1e-10f * da * db) {
        float tau = (db - da) / (2.0f * dot);
        float tt  = 1.0f / (fabsf(tau) + sqrtf(fmaf(tau, tau, 1.0f)));
        tt = copysignf(tt, tau);
        float c  = rsqrtf(fmaf(tt, tt, 1.0f));
        float fp = tt * __fdividef(gb, ga);
        float fq = tt * __fdividef(ga, gb);
        float2 nfp2 = {-fp,-fp}, fq2 = {fq,fq};
#pragma unroll
        for (int k = 0; k < 32; k++) {
            float2 a = A[k];
            A[k] = f2fma(nfp2, B[k], a);
            B[k] = f2fma(fq2,  a,    B[k]);
        }
        da = fmaf(-tt, dot, da);
        db = fmaf( tt, dot, db);
        ga *= c;  gb *= c;
        rot_any = true;
    }
}

// Fold scales into columns and compute exact true norms (sweep-start refresh).
__device__ __forceinline__ void fold_and_norms(float2 (&A)[32], float2 (&B)[32],
                                               float& da, float& db,
                                               float& ga, float& gb)
{
    float2 ga2 = {ga,ga}, gb2 = {gb,gb};
    float2 na0={0,0}, na1={0,0}, nb0={0,0}, nb1={0,0};
#pragma unroll
    for (int k = 0; k < 32; k += 2) {
        A[k]   = f2mul(ga2, A[k]);
        A[k+1] = f2mul(ga2, A[k+1]);
        B[k]   = f2mul(gb2, B[k]);
        B[k+1] = f2mul(gb2, B[k+1]);
        na0 = f2fma(A[k],   A[k],   na0);
        na1 = f2fma(A[k+1], A[k+1], na1);
        nb0 = f2fma(B[k],   B[k],   nb0);
        nb1 = f2fma(B[k+1], B[k+1], nb1);
    }
    da = (na0.x+na0.y)+(na1.x+na1.y);
    db = (nb0.x+nb0.y)+(nb1.x+nb1.y);
    ga = 1.0f;  gb = 1.0f;
}

#define SSTR 66   // smem row stride (floats); even for float2 loads

// One warp per 64x64 SPD matrix. One-sided Jacobi, recursive cross-set
// tournament (63 rounds = all 2016 pairs), fast-Givens scaled rotations.
// Column order is scrambled — harmless: logm = sum_i w_i g_i g_i^T.
// NOTE: launch_bounds(32,10) -> reg cap 204. Do NOT tighten: fast-Givens
// needs ~180+ regs; a 170 cap spills the column arrays (R8 regression).
__global__ __launch_bounds__(32, 10)
void logeig_jacobi(const float* __restrict__ X, float* __restrict__ Out, int nmat)
{
    const int lane = threadIdx.x & 31;
    const int mat  = blockIdx.x;

    __shared__ float sh[64 * SSTR + 64];

    if (mat >= nmat) return;

    const float* Xm = X + (size_t)mat * 4096;
    float*       Om = Out + (size_t)mat * 4096;

    float2 A[32], B[32];

    // X symmetric: column j == row j (contiguous). Lane holds cols lane, lane+32.
    {
        const float4* rT = reinterpret_cast<const float4*>(Xm + lane * 64);
        const float4* rB = reinterpret_cast<const float4*>(Xm + (lane + 32) * 64);
#pragma unroll
        for (int m = 0; m < 16; m++) {
            float4 a = rT[m];
            A[2*m]   = make_float2(a.x, a.y);
            A[2*m+1] = make_float2(a.z, a.w);
            float4 b = rB[m];
            B[2*m]   = make_float2(b.x, b.y);
            B[2*m+1] = make_float2(b.z, b.w);
        }
    }

    float da, db;
    float ga = 1.0f, gb = 1.0f;

    for (int sweep = 0; sweep < 16; sweep++) {
        fold_and_norms(A, B, da, db, ga, gb);
        bool rot_any = false;

#pragma unroll 1
        for (int G = 32; G > 1; G >>= 1) {
            const int g   = lane & (G - 1);
            const int src = (lane ^ g) | ((g + 1) & (G - 1));   // next lane in group

#pragma unroll 1
            for (int r = 0; r < G; r++) {
                if (r) {                 // cycle B within group: pure shuffles
#pragma unroll
                    for (int k = 0; k < 32; k++) {
                        float2 v = B[k];
                        v.x = __shfl_sync(WFULL, v.x, src);
                        v.y = __shfl_sync(WFULL, v.y, src);
                        B[k] = v;
                    }
                    db = __shfl_sync(WFULL, db, src);
                    gb = __shfl_sync(WFULL, gb, src);
                }
                rotate_pair(A, B, da, db, ga, gb, rot_any);
            }

            // Regroup: sub-lanes [0,G/2) collect the A-set, [G/2,G) the B-set.
            {
                const int  h  = G >> 1;
                const bool hi = (lane & h) != 0;
#pragma unroll
                for (int k = 0; k < 32; k++) {
                    float2 a = A[k], b = B[k];
                    float sx = hi ? a.x : b.x;
                    float sy = hi ? a.y : b.y;
                    sx = __shfl_xor_sync(WFULL, sx, h);
                    sy = __shfl_xor_sync(WFULL, sy, h);
                    if (hi) A[k] = make_float2(sx, sy);
                    else    B[k] = make_float2(sx, sy);
                }
                float sd = hi ? da : db;
                float sg = hi ? ga : gb;
                sd = __shfl_xor_sync(WFULL, sd, h);
                sg = __shfl_xor_sync(WFULL, sg, h);
                if (hi) { da = sd; ga = sg; }
                else    { db = sd; gb = sg; }
            }
        }
        rotate_pair(A, B, da, db, ga, gb, rot_any);   // level G==1: local pair

        if (!__any_sync(WFULL, rot_any)) break;
    }

    // ---- Reconstruction: Out = sum_i w_i g_i g_i^T,  w_i = 0.5*log(d_i)/d_i ----
    fold_and_norms(A, B, da, db, ga, gb);   // unscale + exact lambda_i^2

    float* S = sh;                           // S[k*SSTR + slot] = g_slot[k]
    float* w = sh + 64 * SSTR;
#pragma unroll
    for (int k = 0; k < 32; k++) {
        S[(2*k  )*SSTR + lane]      = A[k].x;
        S[(2*k+1)*SSTR + lane]      = A[k].y;
        S[(2*k  )*SSTR + lane + 32] = B[k].x;
        S[(2*k+1)*SSTR + lane + 32] = B[k].y;
    }
    w[lane]      = 0.5f * logf(da) / da;
    w[lane + 32] = 0.5f * logf(db) / db;
    __syncwarp();

    // Reuse A/B registers: A[k] = w.*g[row lane], B[k] = w.*g[row lane+32]
#pragma unroll
    for (int k = 0; k < 32; k++) {
        float2 wk = *reinterpret_cast<const float2*>(w + 2*k);
        float2 g0 = *reinterpret_cast<const float2*>(S + lane*SSTR + 2*k);
        float2 g1 = *reinterpret_cast<const float2*>(S + (lane+32)*SSTR + 2*k);
        A[k] = f2mul(wk, g0);
        B[k] = f2mul(wk, g1);
    }

#pragma unroll 1
    for (int c = 0; c < 64; c += 2) {
        const float2* Sc0 = reinterpret_cast<const float2*>(S + c*SSTR);       // broadcast
        const float2* Sc1 = reinterpret_cast<const float2*>(S + (c+1)*SSTR);
        float2 s0a={0,0}, s0b={0,0}, s1a={0,0}, s1b={0,0};
#pragma unroll
        for (int k = 0; k < 32; k++) {
            float2 g0 = Sc0[k], g1 = Sc1[k];
            s0a = f2fma(A[k], g0, s0a);
            s0b = f2fma(A[k], g1, s0b);
            s1a = f2fma(B[k], g0, s1a);
            s1b = f2fma(B[k], g1, s1b);
        }
        float2 o0 = make_float2(s0a.x+s0a.y, s0b.x+s0b.y);
        float2 o1 = make_float2(s1a.x+s1a.y, s1b.x+s1b.y);
        *reinterpret_cast<float2*>(Om + lane*64 + c)        = o0;   // STG.64
        *reinterpret_cast<float2*>(Om + (lane + 32)*64 + c) = o1;
    }
}

extern "C" void kernel_launch(void* const* d_in, const int* in_sizes, int n_in,
                              void* d_out, int out_size)
{
    const float* X  = (const float*)d_in[0];
    float*       Om = (float*)d_out;
    int nmat = in_sizes[0] / 4096;          // 8192 matrices of 64x64
    logeig_jacobi<<<nmat, 32>>>(X, Om, nmat);
}